// round 1
// baseline (speedup 1.0000x reference)
#include <cuda_runtime.h>

#define N_NODES 100000
#define N_EDGES 1600000
#define E_TOT   (N_EDGES + N_NODES)
#define HID 64
#define N_LAYERS 16
#define N_GRAPHS 64
#define BN_EPS 1e-5f
#define NEG 0.2f

__device__ float d_hp[N_NODES * HID];
__device__ float d_hA[N_NODES * HID];
__device__ float d_hB[N_NODES * HID];
__device__ float d_esrc[N_NODES];
__device__ float d_edst[N_NODES];
__device__ int   d_src32[E_TOT];
__device__ int   d_dst32[E_TOT];
__device__ int   d_csr[E_TOT];
__device__ int   d_rowstart[N_NODES + 1];
__device__ int   d_cursor[N_NODES];
__device__ int   d_deg[N_NODES];
__device__ float d_gsum[N_LAYERS][HID];
__device__ float d_gsq[N_LAYERS][HID];
__device__ float d_scale[N_LAYERS][HID];
__device__ float d_shift[N_LAYERS][HID];
__device__ float d_pooled[N_GRAPHS * HID];
__device__ float d_cnt[N_GRAPHS];
__device__ int   d_flag_e;
__device__ int   d_flag_b;

__global__ void k_zero() {
    int i = blockIdx.x * blockDim.x + threadIdx.x;
    if (i < N_NODES) d_deg[i] = 0;
    if (i < N_LAYERS * HID) { ((float*)d_gsum)[i] = 0.f; ((float*)d_gsq)[i] = 0.f; }
    if (i < N_GRAPHS * HID) d_pooled[i] = 0.f;
    if (i < N_GRAPHS) d_cnt[i] = 0.f;
    if (i == 0) { d_flag_e = 1; d_flag_b = 1; }
}

__global__ void k_detect(const void* p, long n64, long long maxv, int mode) {
    long step = n64 / 256; if (step < 1) step = 1;
    long i = (long)threadIdx.x * step; if (i >= n64) i = n64 - 1;
    long long v = ((const long long*)p)[i];
    if (v < 0 || v >= maxv) atomicAnd(mode ? &d_flag_b : &d_flag_e, 0);
}

__global__ void k_build(const void* eidx) {
    int t = blockIdx.x * blockDim.x + threadIdx.x;
    if (t >= E_TOT) return;
    int s, d;
    if (t < N_EDGES) {
        if (d_flag_e) {
            const long long* p = (const long long*)eidx;
            s = (int)p[t]; d = (int)p[N_EDGES + t];
        } else {
            const int* p = (const int*)eidx;
            s = p[t]; d = p[N_EDGES + t];
        }
    } else {
        s = d = t - N_EDGES;
    }
    d_src32[t] = s; d_dst32[t] = d;
    atomicAdd(&d_deg[d], 1);
}

__global__ void k_scan() {
    __shared__ int sh[1024];
    __shared__ int carry;
    int tid = threadIdx.x;
    if (tid == 0) carry = 0;
    __syncthreads();
    for (int base = 0; base < N_NODES; base += 1024) {
        int i = base + tid;
        int v = (i < N_NODES) ? d_deg[i] : 0;
        sh[tid] = v;
        __syncthreads();
        for (int off = 1; off < 1024; off <<= 1) {
            int t = (tid >= off) ? sh[tid - off] : 0;
            __syncthreads();
            sh[tid] += t;
            __syncthreads();
        }
        int excl = carry + sh[tid] - v;
        if (i < N_NODES) { d_rowstart[i] = excl; d_cursor[i] = excl; }
        __syncthreads();
        if (tid == 1023) carry += sh[1023];
        __syncthreads();
    }
    if (tid == 0) d_rowstart[N_NODES] = carry;
}

__global__ void k_scatter() {
    int t = blockIdx.x * blockDim.x + threadIdx.x;
    if (t >= E_TOT) return;
    int d = d_dst32[t];
    int pos = atomicAdd(&d_cursor[d], 1);
    d_csr[pos] = d_src32[t];
}

// hp = bnrelu(hin) @ W ; bn params taken from d_scale/d_shift[bn_layer] if >= 0
__global__ __launch_bounds__(512) void k_gemm(const float* __restrict__ xin, int src_sel,
                                              const float* __restrict__ W, int bn_layer) {
    const float* hin = (src_sel == 0) ? xin : (src_sel == 1 ? d_hA : d_hB);
    __shared__ float sW[64 * 64];
    __shared__ float sh[32 * 64];
    int c = threadIdx.x, ty = threadIdx.y;
    int tid = ty * 64 + c;
    int row0 = blockIdx.x * 32;
    for (int i = tid; i < 64 * 64; i += 512) sW[i] = W[i];
    for (int i = tid; i < 32 * 64; i += 512) {
        int k = i & 63;
        float v = hin[row0 * 64 + i];
        if (bn_layer >= 0)
            v = fmaxf(v * d_scale[bn_layer][k] + d_shift[bn_layer][k], 0.f);
        sh[i] = v;
    }
    __syncthreads();
    float a0 = 0.f, a1 = 0.f, a2 = 0.f, a3 = 0.f;
#pragma unroll
    for (int k = 0; k < 64; k++) {
        float w = sW[k * 64 + c];
        a0 += sh[ty * 64 + k] * w;
        a1 += sh[(ty + 8) * 64 + k] * w;
        a2 += sh[(ty + 16) * 64 + k] * w;
        a3 += sh[(ty + 24) * 64 + k] * w;
    }
    d_hp[(row0 + ty) * 64 + c]      = a0;
    d_hp[(row0 + ty + 8) * 64 + c]  = a1;
    d_hp[(row0 + ty + 16) * 64 + c] = a2;
    d_hp[(row0 + ty + 24) * 64 + c] = a3;
}

__global__ void k_logits(const float* __restrict__ as, const float* __restrict__ ad) {
    int w = (blockIdx.x * blockDim.x + threadIdx.x) >> 5;
    int lane = threadIdx.x & 31;
    if (w >= N_NODES) return;
    float v0 = d_hp[w * 64 + lane], v1 = d_hp[w * 64 + lane + 32];
    float s = v0 * as[lane] + v1 * as[lane + 32];
    float d = v0 * ad[lane] + v1 * ad[lane + 32];
#pragma unroll
    for (int o = 16; o; o >>= 1) {
        s += __shfl_xor_sync(0xffffffffu, s, o);
        d += __shfl_xor_sync(0xffffffffu, d, o);
    }
    if (!lane) { d_esrc[w] = s; d_edst[w] = d; }
}

__global__ __launch_bounds__(256) void k_agg(const float* __restrict__ bias,
                                             int out_sel, int layer) {
    __shared__ float s_sum[64], s_sq[64];
    float* out = (out_sel == 1) ? d_hA : d_hB;
    int tid = threadIdx.x;
    if (tid < 64) { s_sum[tid] = 0.f; s_sq[tid] = 0.f; }
    __syncthreads();
    int n = blockIdx.x * 8 + (tid >> 5);
    int lane = tid & 31;
    int beg = d_rowstart[n], end = d_rowstart[n + 1];
    float ed = d_edst[n];

    float m = -1e30f;
    for (int i = beg + lane; i < end; i += 32) {
        int s = d_csr[i];
        float e = d_esrc[s] + ed; e = e > 0.f ? e : NEG * e;
        m = fmaxf(m, e);
    }
#pragma unroll
    for (int o = 16; o; o >>= 1) m = fmaxf(m, __shfl_xor_sync(0xffffffffu, m, o));

    float z = 0.f;
    for (int i = beg + lane; i < end; i += 32) {
        int s = d_csr[i];
        float e = d_esrc[s] + ed; e = e > 0.f ? e : NEG * e;
        z += __expf(e - m);
    }
#pragma unroll
    for (int o = 16; o; o >>= 1) z += __shfl_xor_sync(0xffffffffu, z, o);
    float invz = 1.0f / z;

    float a0 = 0.f, a1 = 0.f;
    for (int i = beg; i < end; i++) {
        int s = d_csr[i];
        float e = d_esrc[s] + ed; e = e > 0.f ? e : NEG * e;
        float w = __expf(e - m);
        a0 += w * d_hp[s * 64 + lane];
        a1 += w * d_hp[s * 64 + lane + 32];
    }
    a0 = a0 * invz + bias[lane];
    a1 = a1 * invz + bias[lane + 32];
    out[n * 64 + lane]      = a0;
    out[n * 64 + lane + 32] = a1;
    atomicAdd(&s_sum[lane], a0);       atomicAdd(&s_sq[lane], a0 * a0);
    atomicAdd(&s_sum[lane + 32], a1);  atomicAdd(&s_sq[lane + 32], a1 * a1);
    __syncthreads();
    if (tid < 64) {
        atomicAdd(&d_gsum[layer][tid], s_sum[tid]);
        atomicAdd(&d_gsq[layer][tid], s_sq[tid]);
    }
}

__global__ void k_bn(const float* __restrict__ gamma, const float* __restrict__ beta,
                     int layer) {
    int c = threadIdx.x;
    float mu = d_gsum[layer][c] * (1.0f / N_NODES);
    float var = d_gsq[layer][c] * (1.0f / N_NODES) - mu * mu;
    float s = gamma[c] * rsqrtf(var + BN_EPS);
    d_scale[layer][c] = s;
    d_shift[layer][c] = beta[c] - mu * s;
}

__global__ void k_pool(int src_sel, const void* batch) {
    int w = (blockIdx.x * blockDim.x + threadIdx.x) >> 5;
    int lane = threadIdx.x & 31;
    if (w >= N_NODES) return;
    const float* h = (src_sel == 1) ? d_hA : d_hB;
    int g = d_flag_b ? (int)((const long long*)batch)[w] : ((const int*)batch)[w];
    float v0 = fmaxf(h[w * 64 + lane] * d_scale[15][lane] + d_shift[15][lane], 0.f);
    float v1 = fmaxf(h[w * 64 + lane + 32] * d_scale[15][lane + 32] + d_shift[15][lane + 32], 0.f);
    atomicAdd(&d_pooled[g * 64 + lane], v0);
    atomicAdd(&d_pooled[g * 64 + lane + 32], v1);
    if (!lane) atomicAdd(&d_cnt[g], 1.0f);
}

__global__ void k_mlp(const float* __restrict__ W1, const float* __restrict__ b1,
                      const float* __restrict__ W2, const float* __restrict__ b2,
                      const float* __restrict__ W3, const float* __restrict__ b3,
                      float* __restrict__ out) {
    int g = threadIdx.x;
    if (g >= N_GRAPHS) return;
    float inv = 1.0f / fmaxf(d_cnt[g], 1.0f);
    float p[64];
    for (int i = 0; i < 64; i++) p[i] = d_pooled[g * 64 + i] * inv;
    float h1[50];
    for (int j = 0; j < 50; j++) {
        float s = b1[j];
        for (int i = 0; i < 64; i++) s += p[i] * W1[i * 50 + j];
        h1[j] = fmaxf(s, 0.f);
    }
    float h2[25];
    for (int j = 0; j < 25; j++) {
        float s = b2[j];
        for (int i = 0; i < 50; i++) s += h1[i] * W2[i * 25 + j];
        h2[j] = fmaxf(s, 0.f);
    }
    float s = b3[0];
    for (int i = 0; i < 25; i++) s += h2[i] * W3[i];
    out[g] = s;
}

extern "C" void kernel_launch(void* const* d_in, const int* in_sizes, int n_in,
                              void* d_out, int out_size) {
    const float* x       = (const float*)d_in[0];
    const float* W0      = (const float*)d_in[1];
    const float* Ws      = (const float*)d_in[2];
    const float* att_src = (const float*)d_in[3];
    const float* att_dst = (const float*)d_in[4];
    const float* bias    = (const float*)d_in[5];
    const float* gamma   = (const float*)d_in[6];
    const float* beta    = (const float*)d_in[7];
    const float* mW1 = (const float*)d_in[8];
    const float* mb1 = (const float*)d_in[9];
    const float* mW2 = (const float*)d_in[10];
    const float* mb2 = (const float*)d_in[11];
    const float* mW3 = (const float*)d_in[12];
    const float* mb3 = (const float*)d_in[13];
    const void*  eidx  = d_in[14];
    const void*  batch = d_in[15];

    k_zero<<<(N_NODES + 255) / 256, 256>>>();
    k_detect<<<1, 256>>>(eidx, (long)N_EDGES, (long long)N_NODES, 0);
    k_detect<<<1, 256>>>(batch, (long)(N_NODES / 2), (long long)N_GRAPHS, 1);
    k_build<<<(E_TOT + 255) / 256, 256>>>(eidx);
    k_scan<<<1, 1024>>>();
    k_scatter<<<(E_TOT + 255) / 256, 256>>>();

    dim3 gthreads(64, 8);
    for (int l = 0; l < N_LAYERS; l++) {
        const float* W = (l == 0) ? W0 : (Ws + (size_t)(l - 1) * HID * HID);
        int src_sel = (l == 0) ? 0 : ((l & 1) ? 1 : 2);
        int out_sel = (l & 1) ? 2 : 1;
        k_gemm<<<3125, gthreads>>>(x, src_sel, W, l - 1);
        k_logits<<<12500, 256>>>(att_src + l * HID, att_dst + l * HID);
        k_agg<<<12500, 256>>>(bias + l * HID, out_sel, l);
        k_bn<<<1, 64>>>(gamma + l * HID, beta + l * HID, l);
    }
    k_pool<<<12500, 256>>>(2, batch);
    k_mlp<<<1, 64>>>(mW1, mb1, mW2, mb2, mW3, mb3, (float*)d_out);
}

// round 3
// speedup vs baseline: 1.1014x; 1.1014x over previous
#include <cuda_runtime.h>

#define N_NODES 100000
#define N_EDGES 1600000
#define E_TOT   (N_EDGES + N_NODES)
#define HID 64
#define N_LAYERS 16
#define N_GRAPHS 64
#define BN_EPS 1e-5f
#define NEG 0.2f

__device__ float d_hp[N_NODES * HID];
__device__ float d_hA[N_NODES * HID];
__device__ float d_hB[N_NODES * HID];
__device__ float d_esrc[N_NODES];
__device__ float d_edst[N_NODES];
__device__ float d_ea[E_TOT];               // per-CSR-slot: e, then alpha-numerator
__device__ int   d_src32[E_TOT];
__device__ int   d_dst32[E_TOT];
__device__ int   d_csr[E_TOT];
__device__ int   d_rowstart[N_NODES + 1];
__device__ int   d_cursor[N_NODES];
__device__ int   d_deg[N_NODES];
__device__ float d_gsum[N_LAYERS][HID];
__device__ float d_gsq[N_LAYERS][HID];
__device__ float d_scale[N_LAYERS][HID];
__device__ float d_shift[N_LAYERS][HID];
__device__ float d_pooled[N_GRAPHS * HID];
__device__ float d_cnt[N_GRAPHS];
__device__ int   d_flag_e;
__device__ int   d_flag_b;

__global__ void k_zero() {
    int i = blockIdx.x * blockDim.x + threadIdx.x;
    if (i < N_NODES) d_deg[i] = 0;
    if (i < N_LAYERS * HID) { ((float*)d_gsum)[i] = 0.f; ((float*)d_gsq)[i] = 0.f; }
    if (i < N_GRAPHS * HID) d_pooled[i] = 0.f;
    if (i < N_GRAPHS) d_cnt[i] = 0.f;
    if (i == 0) { d_flag_e = 1; d_flag_b = 1; }
}

__global__ void k_detect(const void* p, long n64, long long maxv, int mode) {
    long step = n64 / 256; if (step < 1) step = 1;
    long i = (long)threadIdx.x * step; if (i >= n64) i = n64 - 1;
    long long v = ((const long long*)p)[i];
    if (v < 0 || v >= maxv) atomicAnd(mode ? &d_flag_b : &d_flag_e, 0);
}

__global__ void k_build(const void* eidx) {
    int t = blockIdx.x * blockDim.x + threadIdx.x;
    if (t >= E_TOT) return;
    int s, d;
    if (t < N_EDGES) {
        if (d_flag_e) {
            const long long* p = (const long long*)eidx;
            s = (int)p[t]; d = (int)p[N_EDGES + t];
        } else {
            const int* p = (const int*)eidx;
            s = p[t]; d = p[N_EDGES + t];
        }
    } else {
        s = d = t - N_EDGES;
    }
    d_src32[t] = s; d_dst32[t] = d;
    atomicAdd(&d_deg[d], 1);
}

__global__ void k_scan() {
    __shared__ int sh[1024];
    __shared__ int carry;
    int tid = threadIdx.x;
    if (tid == 0) carry = 0;
    __syncthreads();
    for (int base = 0; base < N_NODES; base += 1024) {
        int i = base + tid;
        int v = (i < N_NODES) ? d_deg[i] : 0;
        sh[tid] = v;
        __syncthreads();
        for (int off = 1; off < 1024; off <<= 1) {
            int t = (tid >= off) ? sh[tid - off] : 0;
            __syncthreads();
            sh[tid] += t;
            __syncthreads();
        }
        int excl = carry + sh[tid] - v;
        if (i < N_NODES) { d_rowstart[i] = excl; d_cursor[i] = excl; }
        __syncthreads();
        if (tid == 1023) carry += sh[1023];
        __syncthreads();
    }
    if (tid == 0) d_rowstart[N_NODES] = carry;
}

__global__ void k_scatter() {
    int t = blockIdx.x * blockDim.x + threadIdx.x;
    if (t >= E_TOT) return;
    int d = d_dst32[t];
    int pos = atomicAdd(&d_cursor[d], 1);
    d_csr[pos] = d_src32[t];
}

// hp = bnrelu(hin) @ W ; fused attention-logit epilogue (e_src, e_dst).
__global__ __launch_bounds__(512) void k_gemm(const float* __restrict__ xin, int src_sel,
                                              const float* __restrict__ W, int bn_layer,
                                              const float* __restrict__ as,
                                              const float* __restrict__ ad) {
    const float* hin = (src_sel == 0) ? xin : (src_sel == 1 ? d_hA : d_hB);
    __shared__ float sW[64 * 64];
    __shared__ float sh[32 * 64];
    __shared__ float s_red[8][2][4][2];   // [ty][half][rowblk][src/dst]
    int c = threadIdx.x, ty = threadIdx.y;
    int tid = ty * 64 + c;
    int row0 = blockIdx.x * 32;

    // W: 4096 floats = 1024 float4 via 512 threads
    {
        const float4* W4 = (const float4*)W;
        float4* sW4 = (float4*)sW;
        sW4[tid] = W4[tid];
        sW4[tid + 512] = W4[tid + 512];
    }
    // hin tile: 2048 floats = 512 float4
    {
        const float4* H4 = (const float4*)(hin + row0 * 64);
        float4 v = H4[tid];
        if (bn_layer >= 0) {
            int k = (tid & 15) * 4;
            v.x = fmaxf(v.x * d_scale[bn_layer][k]     + d_shift[bn_layer][k],     0.f);
            v.y = fmaxf(v.y * d_scale[bn_layer][k + 1] + d_shift[bn_layer][k + 1], 0.f);
            v.z = fmaxf(v.z * d_scale[bn_layer][k + 2] + d_shift[bn_layer][k + 2], 0.f);
            v.w = fmaxf(v.w * d_scale[bn_layer][k + 3] + d_shift[bn_layer][k + 3], 0.f);
        }
        ((float4*)sh)[tid] = v;
    }
    __syncthreads();

    float a0 = 0.f, a1 = 0.f, a2 = 0.f, a3 = 0.f;
#pragma unroll
    for (int k = 0; k < 64; k++) {
        float w = sW[k * 64 + c];
        a0 += sh[ty * 64 + k] * w;
        a1 += sh[(ty + 8) * 64 + k] * w;
        a2 += sh[(ty + 16) * 64 + k] * w;
        a3 += sh[(ty + 24) * 64 + k] * w;
    }
    d_hp[(row0 + ty) * 64 + c]      = a0;
    d_hp[(row0 + ty + 8) * 64 + c]  = a1;
    d_hp[(row0 + ty + 16) * 64 + c] = a2;
    d_hp[(row0 + ty + 24) * 64 + c] = a3;

    // fused logits: reduce a_r * as[c] and a_r * ad[c] over c
    float asc = as[c], adc = ad[c];
    float rs0 = a0 * asc, rs1 = a1 * asc, rs2 = a2 * asc, rs3 = a3 * asc;
    float rd0 = a0 * adc, rd1 = a1 * adc, rd2 = a2 * adc, rd3 = a3 * adc;
#pragma unroll
    for (int o = 16; o; o >>= 1) {
        rs0 += __shfl_xor_sync(0xffffffffu, rs0, o);
        rs1 += __shfl_xor_sync(0xffffffffu, rs1, o);
        rs2 += __shfl_xor_sync(0xffffffffu, rs2, o);
        rs3 += __shfl_xor_sync(0xffffffffu, rs3, o);
        rd0 += __shfl_xor_sync(0xffffffffu, rd0, o);
        rd1 += __shfl_xor_sync(0xffffffffu, rd1, o);
        rd2 += __shfl_xor_sync(0xffffffffu, rd2, o);
        rd3 += __shfl_xor_sync(0xffffffffu, rd3, o);
    }
    int half = c >> 5;
    if ((c & 31) == 0) {
        s_red[ty][half][0][0] = rs0; s_red[ty][half][0][1] = rd0;
        s_red[ty][half][1][0] = rs1; s_red[ty][half][1][1] = rd1;
        s_red[ty][half][2][0] = rs2; s_red[ty][half][2][1] = rd2;
        s_red[ty][half][3][0] = rs3; s_red[ty][half][3][1] = rd3;
    }
    __syncthreads();
    if (tid < 64) {
        int ty2 = tid >> 3, r = (tid >> 1) & 3, sd = tid & 1;
        float v = s_red[ty2][0][r][sd] + s_red[ty2][1][r][sd];
        int row = row0 + ty2 + r * 8;
        if (sd == 0) d_esrc[row] = v; else d_edst[row] = v;
    }
}

__global__ __launch_bounds__(256) void k_agg(const float* __restrict__ bias,
                                             int out_sel, int layer) {
    __shared__ float s_sum[64], s_sq[64];
    float2* out2 = (float2*)((out_sel == 1) ? d_hA : d_hB);
    const float2* hp2 = (const float2*)d_hp;
    int tid = threadIdx.x;
    if (tid < 64) { s_sum[tid] = 0.f; s_sq[tid] = 0.f; }
    __syncthreads();
    int n = blockIdx.x * 8 + (tid >> 5);
    int lane = tid & 31;
    int beg = d_rowstart[n], end = d_rowstart[n + 1];
    float ed = d_edst[n];

    // pass 1: compute e, store, row max
    float m = -1e30f;
    for (int i = beg + lane; i < end; i += 32) {
        int s = d_csr[i];
        float e = d_esrc[s] + ed; e = e > 0.f ? e : NEG * e;
        d_ea[i] = e;
        m = fmaxf(m, e);
    }
#pragma unroll
    for (int o = 16; o; o >>= 1) m = fmaxf(m, __shfl_xor_sync(0xffffffffu, m, o));

    // pass 2: exp(e-m), store numerator, sum
    float z = 0.f;
    for (int i = beg + lane; i < end; i += 32) {
        float w = __expf(d_ea[i] - m);
        z += w;
        d_ea[i] = w;
    }
#pragma unroll
    for (int o = 16; o; o >>= 1) z += __shfl_xor_sync(0xffffffffu, z, o);
    float invz = 1.0f / z;
    __syncwarp();

    // pass 3: pure weighted gather, float2 per lane, unroll x2
    float2 acc0 = {0.f, 0.f}, acc1 = {0.f, 0.f};
    int i = beg;
    for (; i + 1 < end; i += 2) {
        float w0 = d_ea[i], w1 = d_ea[i + 1];
        int s0 = d_csr[i], s1 = d_csr[i + 1];
        float2 h0 = hp2[s0 * 32 + lane];
        float2 h1 = hp2[s1 * 32 + lane];
        acc0.x += w0 * h0.x; acc0.y += w0 * h0.y;
        acc1.x += w1 * h1.x; acc1.y += w1 * h1.y;
    }
    if (i < end) {
        float w0 = d_ea[i];
        int s0 = d_csr[i];
        float2 h0 = hp2[s0 * 32 + lane];
        acc0.x += w0 * h0.x; acc0.y += w0 * h0.y;
    }
    int c0 = 2 * lane, c1 = 2 * lane + 1;
    float vx = (acc0.x + acc1.x) * invz + bias[c0];
    float vy = (acc0.y + acc1.y) * invz + bias[c1];
    float2 o2; o2.x = vx; o2.y = vy;
    out2[n * 32 + lane] = o2;
    atomicAdd(&s_sum[c0], vx); atomicAdd(&s_sq[c0], vx * vx);
    atomicAdd(&s_sum[c1], vy); atomicAdd(&s_sq[c1], vy * vy);
    __syncthreads();
    if (tid < 64) {
        atomicAdd(&d_gsum[layer][tid], s_sum[tid]);
        atomicAdd(&d_gsq[layer][tid], s_sq[tid]);
    }
}

__global__ void k_bn(const float* __restrict__ gamma, const float* __restrict__ beta,
                     int layer) {
    int c = threadIdx.x;
    float mu = d_gsum[layer][c] * (1.0f / N_NODES);
    float var = d_gsq[layer][c] * (1.0f / N_NODES) - mu * mu;
    float s = gamma[c] * rsqrtf(var + BN_EPS);
    d_scale[layer][c] = s;
    d_shift[layer][c] = beta[c] - mu * s;
}

// global mean pool with smem aggregation for the block's majority graph.
__global__ __launch_bounds__(256) void k_pool(int src_sel, const void* batch) {
    __shared__ float s_pool[64];
    __shared__ int s_cnt;
    __shared__ int s_g0;
    int tid = threadIdx.x;
    int lane = tid & 31;
    if (tid < 64) s_pool[tid] = 0.f;
    if (tid == 0) {
        s_cnt = 0;
        int n0 = blockIdx.x * 8;
        s_g0 = d_flag_b ? (int)((const long long*)batch)[n0] : ((const int*)batch)[n0];
    }
    __syncthreads();
    int n = blockIdx.x * 8 + (tid >> 5);
    const float* h = (src_sel == 1) ? d_hA : d_hB;
    int g = d_flag_b ? (int)((const long long*)batch)[n] : ((const int*)batch)[n];
    int c0 = 2 * lane, c1 = c0 + 1;
    float v0 = fmaxf(h[n * 64 + c0] * d_scale[15][c0] + d_shift[15][c0], 0.f);
    float v1 = fmaxf(h[n * 64 + c1] * d_scale[15][c1] + d_shift[15][c1], 0.f);
    if (g == s_g0) {
        atomicAdd(&s_pool[c0], v0);
        atomicAdd(&s_pool[c1], v1);
        if (!lane) atomicAdd(&s_cnt, 1);
    } else {
        atomicAdd(&d_pooled[g * 64 + c0], v0);
        atomicAdd(&d_pooled[g * 64 + c1], v1);
        if (!lane) atomicAdd(&d_cnt[g], 1.0f);
    }
    __syncthreads();
    if (tid < 64) atomicAdd(&d_pooled[s_g0 * 64 + tid], s_pool[tid]);
    if (tid == 64) atomicAdd(&d_cnt[s_g0], (float)s_cnt);
}

__global__ void k_mlp(const float* __restrict__ W1, const float* __restrict__ b1,
                      const float* __restrict__ W2, const float* __restrict__ b2,
                      const float* __restrict__ W3, const float* __restrict__ b3,
                      float* __restrict__ out) {
    int g = threadIdx.x;
    if (g >= N_GRAPHS) return;
    float inv = 1.0f / fmaxf(d_cnt[g], 1.0f);
    float p[64];
    for (int i = 0; i < 64; i++) p[i] = d_pooled[g * 64 + i] * inv;
    float h1[50];
    for (int j = 0; j < 50; j++) {
        float s = b1[j];
        for (int i = 0; i < 64; i++) s += p[i] * W1[i * 50 + j];
        h1[j] = fmaxf(s, 0.f);
    }
    float h2[25];
    for (int j = 0; j < 25; j++) {
        float s = b2[j];
        for (int i = 0; i < 50; i++) s += h1[i] * W2[i * 25 + j];
        h2[j] = fmaxf(s, 0.f);
    }
    float s = b3[0];
    for (int i = 0; i < 25; i++) s += h2[i] * W3[i];
    out[g] = s;
}

extern "C" void kernel_launch(void* const* d_in, const int* in_sizes, int n_in,
                              void* d_out, int out_size) {
    const float* x       = (const float*)d_in[0];
    const float* W0      = (const float*)d_in[1];
    const float* Ws      = (const float*)d_in[2];
    const float* att_src = (const float*)d_in[3];
    const float* att_dst = (const float*)d_in[4];
    const float* bias    = (const float*)d_in[5];
    const float* gamma   = (const float*)d_in[6];
    const float* beta    = (const float*)d_in[7];
    const float* mW1 = (const float*)d_in[8];
    const float* mb1 = (const float*)d_in[9];
    const float* mW2 = (const float*)d_in[10];
    const float* mb2 = (const float*)d_in[11];
    const float* mW3 = (const float*)d_in[12];
    const float* mb3 = (const float*)d_in[13];
    const void*  eidx  = d_in[14];
    const void*  batch = d_in[15];

    k_zero<<<(N_NODES + 255) / 256, 256>>>();
    k_detect<<<1, 256>>>(eidx, (long)N_EDGES, (long long)N_NODES, 0);
    k_detect<<<1, 256>>>(batch, (long)(N_NODES / 2), (long long)N_GRAPHS, 1);
    k_build<<<(E_TOT + 255) / 256, 256>>>(eidx);
    k_scan<<<1, 1024>>>();
    k_scatter<<<(E_TOT + 255) / 256, 256>>>();

    dim3 gthreads(64, 8);
    for (int l = 0; l < N_LAYERS; l++) {
        const float* W = (l == 0) ? W0 : (Ws + (size_t)(l - 1) * HID * HID);
        int src_sel = (l == 0) ? 0 : ((l & 1) ? 1 : 2);
        int out_sel = (l & 1) ? 2 : 1;
        k_gemm<<<3125, gthreads>>>(x, src_sel, W, l - 1,
                                   att_src + l * HID, att_dst + l * HID);
        k_agg<<<12500, 256>>>(bias + l * HID, out_sel, l);
        k_bn<<<1, 64>>>(gamma + l * HID, beta + l * HID, l);
    }
    k_pool<<<12500, 256>>>(2, batch);
    k_mlp<<<1, 64>>>(mW1, mb1, mW2, mb2, mW3, mb3, (float*)d_out);
}

// round 5
// speedup vs baseline: 1.4326x; 1.3006x over previous
#include <cuda_runtime.h>

#define N_NODES 100000
#define N_EDGES 1600000
#define E_TOT   (N_EDGES + N_NODES)
#define HID 64
#define N_LAYERS 16
#define N_GRAPHS 64
#define BN_EPS 1e-5f
#define NEG 0.2f
#define SCAN_BLOCKS ((N_NODES + 1023) / 1024)

__device__ float d_hp[N_NODES * HID];
__device__ float d_hA[N_NODES * HID];
__device__ float d_hB[N_NODES * HID];
__device__ float d_esrc[N_NODES];
__device__ float d_edst[N_NODES];
__device__ float d_ea[E_TOT];
__device__ int   d_src32[E_TOT];
__device__ int   d_dst32[E_TOT];
__device__ int   d_csr[E_TOT];
__device__ int   d_rowstart[N_NODES + 1];
__device__ int   d_cursor[N_NODES];
__device__ int   d_deg[N_NODES];
__device__ int   d_blksum[128];
__device__ int   d_blkoff[128];
__device__ float d_gsum[N_LAYERS][HID];
__device__ float d_gsq[N_LAYERS][HID];
__device__ float d_pooled[N_GRAPHS * HID];
__device__ float d_cnt[N_GRAPHS];
__device__ int   d_flag_e;
__device__ int   d_flag_b;

__global__ void k_zero() {
    int i = blockIdx.x * blockDim.x + threadIdx.x;
    if (i < N_NODES) d_deg[i] = 0;
    if (i < N_LAYERS * HID) { ((float*)d_gsum)[i] = 0.f; ((float*)d_gsq)[i] = 0.f; }
    if (i < N_GRAPHS * HID) d_pooled[i] = 0.f;
    if (i < N_GRAPHS) d_cnt[i] = 0.f;
    if (i == 0) { d_flag_e = 1; d_flag_b = 1; }
}

__global__ void k_detect(const void* p, long n64, long long maxv, int mode) {
    long step = n64 / 256; if (step < 1) step = 1;
    long i = (long)threadIdx.x * step; if (i >= n64) i = n64 - 1;
    long long v = ((const long long*)p)[i];
    if (v < 0 || v >= maxv) atomicAnd(mode ? &d_flag_b : &d_flag_e, 0);
}

__global__ void k_build(const void* eidx) {
    int t = blockIdx.x * blockDim.x + threadIdx.x;
    if (t >= E_TOT) return;
    int s, d;
    if (t < N_EDGES) {
        if (d_flag_e) {
            const long long* p = (const long long*)eidx;
            s = (int)p[t]; d = (int)p[N_EDGES + t];
        } else {
            const int* p = (const int*)eidx;
            s = p[t]; d = p[N_EDGES + t];
        }
    } else {
        s = d = t - N_EDGES;
    }
    d_src32[t] = s; d_dst32[t] = d;
    atomicAdd(&d_deg[d], 1);
}

// hierarchical scan: local block scans, block-sum scan, then offset fixup
__global__ __launch_bounds__(1024) void k_scan1() {
    __shared__ int sh[1024];
    int tid = threadIdx.x;
    int i = blockIdx.x * 1024 + tid;
    int v = (i < N_NODES) ? d_deg[i] : 0;
    sh[tid] = v;
    __syncthreads();
    for (int off = 1; off < 1024; off <<= 1) {
        int t = (tid >= off) ? sh[tid - off] : 0;
        __syncthreads();
        sh[tid] += t;
        __syncthreads();
    }
    if (i < N_NODES) d_rowstart[i] = sh[tid] - v;    // local exclusive
    if (tid == 1023) d_blksum[blockIdx.x] = sh[1023];
}

__global__ void k_scan2() {
    __shared__ int sh[128];
    int tid = threadIdx.x;
    int v = (tid < SCAN_BLOCKS) ? d_blksum[tid] : 0;
    sh[tid] = v;
    __syncthreads();
    for (int off = 1; off < 128; off <<= 1) {
        int t = (tid >= off) ? sh[tid - off] : 0;
        __syncthreads();
        sh[tid] += t;
        __syncthreads();
    }
    if (tid < SCAN_BLOCKS) d_blkoff[tid] = sh[tid] - v;
    if (tid == SCAN_BLOCKS - 1) d_rowstart[N_NODES] = sh[tid];
}

__global__ __launch_bounds__(1024) void k_scan3() {
    int i = blockIdx.x * 1024 + threadIdx.x;
    if (i < N_NODES) {
        int r = d_rowstart[i] + d_blkoff[blockIdx.x];
        d_rowstart[i] = r;
        d_cursor[i] = r;
    }
}

__global__ void k_scatter() {
    int t = blockIdx.x * blockDim.x + threadIdx.x;
    if (t >= E_TOT) return;
    int d = d_dst32[t];
    int pos = atomicAdd(&d_cursor[d], 1);
    d_csr[pos] = d_src32[t];
}

// hp = bnrelu(hin) @ W, fused BN-param compute + attention-logit epilogue.
// 64x64 output tile per block, 256 threads, 4x4 register microtile.
__global__ __launch_bounds__(256) void k_gemm(const float* __restrict__ xin, int src_sel,
                                              const float* __restrict__ W, int bn_layer,
                                              const float* __restrict__ as,
                                              const float* __restrict__ ad,
                                              const float* __restrict__ gm,
                                              const float* __restrict__ bt) {
    const float* hin = (src_sel == 0) ? xin : (src_sel == 1 ? d_hA : d_hB);
    __shared__ float sW[64 * 64];        // [k][c]
    __shared__ float shT[64 * 68];       // [k][r], padded stride
    __shared__ float s_scale[64], s_shift[64];
    int tid = threadIdx.x;
    int row0 = blockIdx.x * 64;

    if (bn_layer >= 0 && tid < 64) {
        float mu = d_gsum[bn_layer][tid] * (1.0f / N_NODES);
        float var = d_gsq[bn_layer][tid] * (1.0f / N_NODES) - mu * mu;
        float s = gm[tid] * rsqrtf(var + BN_EPS);
        s_scale[tid] = s;
        s_shift[tid] = bt[tid] - mu * s;
    }
    __syncthreads();

    {
        const float4* W4 = (const float4*)W;
        float4* sW4 = (float4*)sW;
#pragma unroll
        for (int i = 0; i < 4; i++) sW4[tid + 256 * i] = W4[tid + 256 * i];
    }
#pragma unroll
    for (int i = 0; i < 4; i++) {
        int f = tid + 256 * i;
        int r = f >> 4, k4 = (f & 15) * 4;
        int gr = row0 + r; if (gr > N_NODES - 1) gr = N_NODES - 1;
        float4 v = *(const float4*)(hin + gr * 64 + k4);
        if (bn_layer >= 0) {
            v.x = fmaxf(v.x * s_scale[k4]     + s_shift[k4],     0.f);
            v.y = fmaxf(v.y * s_scale[k4 + 1] + s_shift[k4 + 1], 0.f);
            v.z = fmaxf(v.z * s_scale[k4 + 2] + s_shift[k4 + 2], 0.f);
            v.w = fmaxf(v.w * s_scale[k4 + 3] + s_shift[k4 + 3], 0.f);
        }
        shT[(k4 + 0) * 68 + r] = v.x;
        shT[(k4 + 1) * 68 + r] = v.y;
        shT[(k4 + 2) * 68 + r] = v.z;
        shT[(k4 + 3) * 68 + r] = v.w;
    }
    __syncthreads();

    int tx = tid & 15, ty = tid >> 4;
    float4 c0 = {0,0,0,0}, c1 = {0,0,0,0}, c2 = {0,0,0,0}, c3 = {0,0,0,0};
#pragma unroll
    for (int k = 0; k < 64; k++) {
        float4 b = *(const float4*)&sW[k * 64 + 4 * tx];
        float4 a = *(const float4*)&shT[k * 68 + 4 * ty];
        c0.x += a.x * b.x; c0.y += a.x * b.y; c0.z += a.x * b.z; c0.w += a.x * b.w;
        c1.x += a.y * b.x; c1.y += a.y * b.y; c1.z += a.y * b.z; c1.w += a.y * b.w;
        c2.x += a.z * b.x; c2.y += a.z * b.y; c2.z += a.z * b.z; c2.w += a.z * b.w;
        c3.x += a.w * b.x; c3.y += a.w * b.y; c3.z += a.w * b.z; c3.w += a.w * b.w;
    }

    int gr0 = row0 + 4 * ty;
    if (gr0 + 0 < N_NODES) *(float4*)(d_hp + (gr0 + 0) * 64 + 4 * tx) = c0;
    if (gr0 + 1 < N_NODES) *(float4*)(d_hp + (gr0 + 1) * 64 + 4 * tx) = c1;
    if (gr0 + 2 < N_NODES) *(float4*)(d_hp + (gr0 + 2) * 64 + 4 * tx) = c2;
    if (gr0 + 3 < N_NODES) *(float4*)(d_hp + (gr0 + 3) * 64 + 4 * tx) = c3;

    // fused logits: per-row dot with as/ad, reduce over tx (lane bits 0..3)
    float4 a4 = *(const float4*)&as[4 * tx];
    float4 d4 = *(const float4*)&ad[4 * tx];
    float rs0 = c0.x*a4.x + c0.y*a4.y + c0.z*a4.z + c0.w*a4.w;
    float rs1 = c1.x*a4.x + c1.y*a4.y + c1.z*a4.z + c1.w*a4.w;
    float rs2 = c2.x*a4.x + c2.y*a4.y + c2.z*a4.z + c2.w*a4.w;
    float rs3 = c3.x*a4.x + c3.y*a4.y + c3.z*a4.z + c3.w*a4.w;
    float rd0 = c0.x*d4.x + c0.y*d4.y + c0.z*d4.z + c0.w*d4.w;
    float rd1 = c1.x*d4.x + c1.y*d4.y + c1.z*d4.z + c1.w*d4.w;
    float rd2 = c2.x*d4.x + c2.y*d4.y + c2.z*d4.z + c2.w*d4.w;
    float rd3 = c3.x*d4.x + c3.y*d4.y + c3.z*d4.z + c3.w*d4.w;
#pragma unroll
    for (int o = 1; o < 16; o <<= 1) {
        rs0 += __shfl_xor_sync(0xffffffffu, rs0, o);
        rs1 += __shfl_xor_sync(0xffffffffu, rs1, o);
        rs2 += __shfl_xor_sync(0xffffffffu, rs2, o);
        rs3 += __shfl_xor_sync(0xffffffffu, rs3, o);
        rd0 += __shfl_xor_sync(0xffffffffu, rd0, o);
        rd1 += __shfl_xor_sync(0xffffffffu, rd1, o);
        rd2 += __shfl_xor_sync(0xffffffffu, rd2, o);
        rd3 += __shfl_xor_sync(0xffffffffu, rd3, o);
    }
    if (tx == 0) {
        if (gr0 + 0 < N_NODES) { d_esrc[gr0 + 0] = rs0; d_edst[gr0 + 0] = rd0; }
        if (gr0 + 1 < N_NODES) { d_esrc[gr0 + 1] = rs1; d_edst[gr0 + 1] = rd1; }
        if (gr0 + 2 < N_NODES) { d_esrc[gr0 + 2] = rs2; d_edst[gr0 + 2] = rd2; }
        if (gr0 + 3 < N_NODES) { d_esrc[gr0 + 3] = rs3; d_edst[gr0 + 3] = rd3; }
    }
}

// softmax aggregation: warp per node, 2 passes (no max-shift: logits are O(1),
// exp cannot overflow; softmax is shift-invariant).
__global__ __launch_bounds__(256) void k_agg(const float* __restrict__ bias,
                                             int out_sel, int layer) {
    __shared__ float s_sum[64], s_sq[64];
    int tid = threadIdx.x;
    if (tid < 64) { s_sum[tid] = 0.f; s_sq[tid] = 0.f; }
    __syncthreads();
    int n = blockIdx.x * 8 + (tid >> 5);
    int lane = tid & 31;
    int beg = d_rowstart[n], end = d_rowstart[n + 1];
    float ed = d_edst[n];

    // pass A: w = exp(leaky(e)), store, sum
    float z = 0.f;
    for (int i = beg + lane; i < end; i += 32) {
        int s = d_csr[i];
        float e = d_esrc[s] + ed; e = e > 0.f ? e : NEG * e;
        float w = __expf(e);
        d_ea[i] = w;
        z += w;
    }
#pragma unroll
    for (int o = 16; o; o >>= 1) z += __shfl_xor_sync(0xffffffffu, z, o);
    float invz = 1.0f / z;
    __syncwarp();

    // pass B: 2 edges per warp, float4 per lane (16 lanes per edge), unroll x2
    int half = lane >> 4, q = lane & 15;
    const float4* hp4 = (const float4*)d_hp;
    float4 acc0 = {0,0,0,0}, acc1 = {0,0,0,0};
    int i = beg;
    for (; i + 4 <= end; i += 4) {
        int e0 = i + half, e1 = i + 2 + half;
        int s0 = d_csr[e0]; float w0 = d_ea[e0];
        int s1 = d_csr[e1]; float w1 = d_ea[e1];
        float4 h0 = hp4[s0 * 16 + q];
        float4 h1 = hp4[s1 * 16 + q];
        acc0.x += w0 * h0.x; acc0.y += w0 * h0.y; acc0.z += w0 * h0.z; acc0.w += w0 * h0.w;
        acc1.x += w1 * h1.x; acc1.y += w1 * h1.y; acc1.z += w1 * h1.z; acc1.w += w1 * h1.w;
    }
    for (; i < end; i += 2) {
        int e0 = i + half;
        float w0 = 0.f; int s0 = 0;
        if (e0 < end) { s0 = d_csr[e0]; w0 = d_ea[e0]; }
        float4 h0 = hp4[s0 * 16 + q];
        acc0.x += w0 * h0.x; acc0.y += w0 * h0.y; acc0.z += w0 * h0.z; acc0.w += w0 * h0.w;
    }
    acc0.x += acc1.x; acc0.y += acc1.y; acc0.z += acc1.z; acc0.w += acc1.w;
    acc0.x += __shfl_xor_sync(0xffffffffu, acc0.x, 16);
    acc0.y += __shfl_xor_sync(0xffffffffu, acc0.y, 16);
    acc0.z += __shfl_xor_sync(0xffffffffu, acc0.z, 16);
    acc0.w += __shfl_xor_sync(0xffffffffu, acc0.w, 16);
    if (half == 0) {
        float4 b4 = *(const float4*)&bias[4 * q];
        float4 v;
        v.x = acc0.x * invz + b4.x;
        v.y = acc0.y * invz + b4.y;
        v.z = acc0.z * invz + b4.z;
        v.w = acc0.w * invz + b4.w;
        float4* out4 = (float4*)((out_sel == 1) ? d_hA : d_hB);
        out4[n * 16 + q] = v;
        int c = 4 * q;
        atomicAdd(&s_sum[c + 0], v.x); atomicAdd(&s_sq[c + 0], v.x * v.x);
        atomicAdd(&s_sum[c + 1], v.y); atomicAdd(&s_sq[c + 1], v.y * v.y);
        atomicAdd(&s_sum[c + 2], v.z); atomicAdd(&s_sq[c + 2], v.z * v.z);
        atomicAdd(&s_sum[c + 3], v.w); atomicAdd(&s_sq[c + 3], v.w * v.w);
    }
    __syncthreads();
    if (tid < 64) {
        atomicAdd(&d_gsum[layer][tid], s_sum[tid]);
        atomicAdd(&d_gsq[layer][tid], s_sq[tid]);
    }
}

// global mean pool, BN of last layer computed inline
__global__ __launch_bounds__(256) void k_pool(int src_sel, const void* batch,
                                              const float* __restrict__ gm,
                                              const float* __restrict__ bt) {
    __shared__ float s_pool[64];
    __shared__ float s_sc[64], s_sh[64];
    __shared__ int s_cnt;
    __shared__ int s_g0;
    int tid = threadIdx.x;
    int lane = tid & 31;
    if (tid < 64) {
        s_pool[tid] = 0.f;
        float mu = d_gsum[N_LAYERS - 1][tid] * (1.0f / N_NODES);
        float var = d_gsq[N_LAYERS - 1][tid] * (1.0f / N_NODES) - mu * mu;
        float s = gm[tid] * rsqrtf(var + BN_EPS);
        s_sc[tid] = s;
        s_sh[tid] = bt[tid] - mu * s;
    }
    if (tid == 0) {
        s_cnt = 0;
        int n0 = blockIdx.x * 8;
        s_g0 = d_flag_b ? (int)((const long long*)batch)[n0] : ((const int*)batch)[n0];
    }
    __syncthreads();
    int n = blockIdx.x * 8 + (tid >> 5);
    const float* h = (src_sel == 1) ? d_hA : d_hB;
    int g = d_flag_b ? (int)((const long long*)batch)[n] : ((const int*)batch)[n];
    int c0 = 2 * lane, c1 = c0 + 1;
    float v0 = fmaxf(h[n * 64 + c0] * s_sc[c0] + s_sh[c0], 0.f);
    float v1 = fmaxf(h[n * 64 + c1] * s_sc[c1] + s_sh[c1], 0.f);
    if (g == s_g0) {
        atomicAdd(&s_pool[c0], v0);
        atomicAdd(&s_pool[c1], v1);
        if (!lane) atomicAdd(&s_cnt, 1);
    } else {
        atomicAdd(&d_pooled[g * 64 + c0], v0);
        atomicAdd(&d_pooled[g * 64 + c1], v1);
        if (!lane) atomicAdd(&d_cnt[g], 1.0f);
    }
    __syncthreads();
    if (tid < 64) atomicAdd(&d_pooled[s_g0 * 64 + tid], s_pool[tid]);
    if (tid == 64) atomicAdd(&d_cnt[s_g0], (float)s_cnt);
}

__global__ void k_mlp(const float* __restrict__ W1, const float* __restrict__ b1,
                      const float* __restrict__ W2, const float* __restrict__ b2,
                      const float* __restrict__ W3, const float* __restrict__ b3,
                      float* __restrict__ out) {
    int g = threadIdx.x;
    if (g >= N_GRAPHS) return;
    float inv = 1.0f / fmaxf(d_cnt[g], 1.0f);
    float p[64];
    for (int i = 0; i < 64; i++) p[i] = d_pooled[g * 64 + i] * inv;
    float h1[50];
    for (int j = 0; j < 50; j++) {
        float s = b1[j];
        for (int i = 0; i < 64; i++) s += p[i] * W1[i * 50 + j];
        h1[j] = fmaxf(s, 0.f);
    }
    float h2[25];
    for (int j = 0; j < 25; j++) {
        float s = b2[j];
        for (int i = 0; i < 50; i++) s += h1[i] * W2[i * 25 + j];
        h2[j] = fmaxf(s, 0.f);
    }
    float s = b3[0];
    for (int i = 0; i < 25; i++) s += h2[i] * W3[i];
    out[g] = s;
}

extern "C" void kernel_launch(void* const* d_in, const int* in_sizes, int n_in,
                              void* d_out, int out_size) {
    const float* x       = (const float*)d_in[0];
    const float* W0      = (const float*)d_in[1];
    const float* Ws      = (const float*)d_in[2];
    const float* att_src = (const float*)d_in[3];
    const float* att_dst = (const float*)d_in[4];
    const float* bias    = (const float*)d_in[5];
    const float* gamma   = (const float*)d_in[6];
    const float* beta    = (const float*)d_in[7];
    const float* mW1 = (const float*)d_in[8];
    const float* mb1 = (const float*)d_in[9];
    const float* mW2 = (const float*)d_in[10];
    const float* mb2 = (const float*)d_in[11];
    const float* mW3 = (const float*)d_in[12];
    const float* mb3 = (const float*)d_in[13];
    const void*  eidx  = d_in[14];
    const void*  batch = d_in[15];

    k_zero<<<(N_NODES + 255) / 256, 256>>>();
    k_detect<<<1, 256>>>(eidx, (long)N_EDGES, (long long)N_NODES, 0);
    k_detect<<<1, 256>>>(batch, (long)(N_NODES / 2), (long long)N_GRAPHS, 1);
    k_build<<<(E_TOT + 255) / 256, 256>>>(eidx);
    k_scan1<<<SCAN_BLOCKS, 1024>>>();
    k_scan2<<<1, 128>>>();
    k_scan3<<<SCAN_BLOCKS, 1024>>>();
    k_scatter<<<(E_TOT + 255) / 256, 256>>>();

    for (int l = 0; l < N_LAYERS; l++) {
        const float* W = (l == 0) ? W0 : (Ws + (size_t)(l - 1) * HID * HID);
        int src_sel = (l == 0) ? 0 : ((l & 1) ? 1 : 2);
        int out_sel = (l & 1) ? 2 : 1;
        const float* gm = gamma + (l > 0 ? (l - 1) : 0) * HID;
        const float* bt = beta + (l > 0 ? (l - 1) : 0) * HID;
        k_gemm<<<(N_NODES + 63) / 64, 256>>>(x, src_sel, W, l - 1,
                                             att_src + l * HID, att_dst + l * HID,
                                             gm, bt);
        k_agg<<<12500, 256>>>(bias + l * HID, out_sel, l);
    }
    k_pool<<<12500, 256>>>(2, batch, gamma + 15 * HID, beta + 15 * HID);
    k_mlp<<<1, 64>>>(mW1, mb1, mW2, mb2, mW3, mb3, (float*)d_out);
}

// round 7
// speedup vs baseline: 1.4333x; 1.0005x over previous
#include <cuda_runtime.h>

#define N_NODES 100000
#define N_EDGES 1600000
#define E_TOT   (N_EDGES + N_NODES)
#define HID 64
#define N_LAYERS 16
#define N_GRAPHS 64
#define BN_EPS 1e-5f
#define NEG 0.2f
#define SCAN_BLOCKS ((N_NODES + 1023) / 1024)

__device__ float d_hp[N_NODES * HID];
__device__ float d_hA[N_NODES * HID];
__device__ float d_hB[N_NODES * HID];
__device__ float d_esrc[N_NODES];
__device__ float d_edst[N_NODES];
__device__ int   d_src32[E_TOT];
__device__ int   d_dst32[E_TOT];
__device__ int   d_csr[E_TOT];
__device__ int   d_rowstart[N_NODES + 1];
__device__ int   d_cursor[N_NODES];
__device__ int   d_deg[N_NODES];
__device__ int   d_blksum[128];
__device__ int   d_blkoff[128];
__device__ float d_gsum[N_LAYERS][HID];
__device__ float d_gsq[N_LAYERS][HID];
__device__ float d_pooled[N_GRAPHS * HID];
__device__ float d_cnt[N_GRAPHS];
__device__ int   d_flag_e;
__device__ int   d_flag_b;

// ---- packed f32x2 helpers (Blackwell) ----
__device__ __forceinline__ unsigned long long pk2(float lo, float hi) {
    unsigned long long r;
    asm("mov.b64 %0, {%1, %2};" : "=l"(r)
        : "r"(__float_as_uint(lo)), "r"(__float_as_uint(hi)));
    return r;
}
__device__ __forceinline__ void fma2(unsigned long long& d,
                                     unsigned long long a, unsigned long long b) {
    asm("fma.rn.f32x2 %0, %1, %2, %3;" : "=l"(d) : "l"(a), "l"(b), "l"(d));
}
__device__ __forceinline__ float2 upk2(unsigned long long v) {
    unsigned int lo, hi;
    asm("mov.b64 {%0, %1}, %2;" : "=r"(lo), "=r"(hi) : "l"(v));
    return make_float2(__uint_as_float(lo), __uint_as_float(hi));
}

__global__ void k_zero() {
    int i = blockIdx.x * blockDim.x + threadIdx.x;
    if (i < N_NODES) d_deg[i] = 0;
    if (i < N_LAYERS * HID) { ((float*)d_gsum)[i] = 0.f; ((float*)d_gsq)[i] = 0.f; }
    if (i < N_GRAPHS * HID) d_pooled[i] = 0.f;
    if (i < N_GRAPHS) d_cnt[i] = 0.f;
    if (i == 0) { d_flag_e = 1; d_flag_b = 1; }
}

__global__ void k_detect(const void* p, long n64, long long maxv, int mode) {
    long step = n64 / 256; if (step < 1) step = 1;
    long i = (long)threadIdx.x * step; if (i >= n64) i = n64 - 1;
    long long v = ((const long long*)p)[i];
    if (v < 0 || v >= maxv) atomicAnd(mode ? &d_flag_b : &d_flag_e, 0);
}

__global__ void k_build(const void* eidx) {
    int t = blockIdx.x * blockDim.x + threadIdx.x;
    if (t >= E_TOT) return;
    int s, d;
    if (t < N_EDGES) {
        if (d_flag_e) {
            const long long* p = (const long long*)eidx;
            s = (int)p[t]; d = (int)p[N_EDGES + t];
        } else {
            const int* p = (const int*)eidx;
            s = p[t]; d = p[N_EDGES + t];
        }
    } else {
        s = d = t - N_EDGES;
    }
    d_src32[t] = s; d_dst32[t] = d;
    atomicAdd(&d_deg[d], 1);
}

__global__ __launch_bounds__(1024) void k_scan1() {
    __shared__ int sh[1024];
    int tid = threadIdx.x;
    int i = blockIdx.x * 1024 + tid;
    int v = (i < N_NODES) ? d_deg[i] : 0;
    sh[tid] = v;
    __syncthreads();
    for (int off = 1; off < 1024; off <<= 1) {
        int t = (tid >= off) ? sh[tid - off] : 0;
        __syncthreads();
        sh[tid] += t;
        __syncthreads();
    }
    if (i < N_NODES) d_rowstart[i] = sh[tid] - v;
    if (tid == 1023) d_blksum[blockIdx.x] = sh[1023];
}

__global__ void k_scan2() {
    __shared__ int sh[128];
    int tid = threadIdx.x;
    int v = (tid < SCAN_BLOCKS) ? d_blksum[tid] : 0;
    sh[tid] = v;
    __syncthreads();
    for (int off = 1; off < 128; off <<= 1) {
        int t = (tid >= off) ? sh[tid - off] : 0;
        __syncthreads();
        sh[tid] += t;
        __syncthreads();
    }
    if (tid < SCAN_BLOCKS) d_blkoff[tid] = sh[tid] - v;
    if (tid == SCAN_BLOCKS - 1) d_rowstart[N_NODES] = sh[tid];
}

__global__ __launch_bounds__(1024) void k_scan3() {
    int i = blockIdx.x * 1024 + threadIdx.x;
    if (i < N_NODES) {
        int r = d_rowstart[i] + d_blkoff[blockIdx.x];
        d_rowstart[i] = r;
        d_cursor[i] = r;
    }
}

__global__ void k_scatter() {
    int t = blockIdx.x * blockDim.x + threadIdx.x;
    if (t >= E_TOT) return;
    int d = d_dst32[t];
    int pos = atomicAdd(&d_cursor[d], 1);
    d_csr[pos] = d_src32[t];
}

// hp = bnrelu(hin) @ W, fused BN-param compute + attention-logit epilogue.
// 64x64 tile / block, 256 threads, 4x4 microtile with packed f32x2 FMA.
__global__ __launch_bounds__(256) void k_gemm(const float* __restrict__ xin, int src_sel,
                                              const float* __restrict__ W, int bn_layer,
                                              const float* __restrict__ as,
                                              const float* __restrict__ ad,
                                              const float* __restrict__ gm,
                                              const float* __restrict__ bt) {
    const float* hin = (src_sel == 0) ? xin : (src_sel == 1 ? d_hA : d_hB);
    __shared__ float sW[64 * 64];        // [k][c]
    __shared__ float shT[64 * 68];       // [k][r], padded stride
    __shared__ float s_scale[64], s_shift[64];
    int tid = threadIdx.x;
    int row0 = blockIdx.x * 64;

    if (bn_layer >= 0 && tid < 64) {
        float mu = d_gsum[bn_layer][tid] * (1.0f / N_NODES);
        float var = d_gsq[bn_layer][tid] * (1.0f / N_NODES) - mu * mu;
        float s = gm[tid] * rsqrtf(var + BN_EPS);
        s_scale[tid] = s;
        s_shift[tid] = bt[tid] - mu * s;
    }
    __syncthreads();

    {
        const float4* W4 = (const float4*)W;
        float4* sW4 = (float4*)sW;
#pragma unroll
        for (int i = 0; i < 4; i++) sW4[tid + 256 * i] = W4[tid + 256 * i];
    }
#pragma unroll
    for (int i = 0; i < 4; i++) {
        int f = tid + 256 * i;
        int r = f >> 4, k4 = (f & 15) * 4;
        int gr = row0 + r; if (gr > N_NODES - 1) gr = N_NODES - 1;
        float4 v = *(const float4*)(hin + gr * 64 + k4);
        if (bn_layer >= 0) {
            v.x = fmaxf(v.x * s_scale[k4]     + s_shift[k4],     0.f);
            v.y = fmaxf(v.y * s_scale[k4 + 1] + s_shift[k4 + 1], 0.f);
            v.z = fmaxf(v.z * s_scale[k4 + 2] + s_shift[k4 + 2], 0.f);
            v.w = fmaxf(v.w * s_scale[k4 + 3] + s_shift[k4 + 3], 0.f);
        }
        shT[(k4 + 0) * 68 + r] = v.x;
        shT[(k4 + 1) * 68 + r] = v.y;
        shT[(k4 + 2) * 68 + r] = v.z;
        shT[(k4 + 3) * 68 + r] = v.w;
    }
    __syncthreads();

    int tx = tid & 15, ty = tid >> 4;
    unsigned long long q00 = 0, q01 = 0, q10 = 0, q11 = 0;
    unsigned long long q20 = 0, q21 = 0, q30 = 0, q31 = 0;
#pragma unroll
    for (int k = 0; k < 64; k++) {
        float4 b = *(const float4*)&sW[k * 64 + 4 * tx];
        float4 a = *(const float4*)&shT[k * 68 + 4 * ty];
        unsigned long long bxy = pk2(b.x, b.y), bzw = pk2(b.z, b.w);
        unsigned long long ax = pk2(a.x, a.x), ay = pk2(a.y, a.y);
        unsigned long long az = pk2(a.z, a.z), aw = pk2(a.w, a.w);
        fma2(q00, ax, bxy); fma2(q01, ax, bzw);
        fma2(q10, ay, bxy); fma2(q11, ay, bzw);
        fma2(q20, az, bxy); fma2(q21, az, bzw);
        fma2(q30, aw, bxy); fma2(q31, aw, bzw);
    }
    float2 t;
    float4 c0, c1, c2, c3;
    t = upk2(q00); c0.x = t.x; c0.y = t.y;  t = upk2(q01); c0.z = t.x; c0.w = t.y;
    t = upk2(q10); c1.x = t.x; c1.y = t.y;  t = upk2(q11); c1.z = t.x; c1.w = t.y;
    t = upk2(q20); c2.x = t.x; c2.y = t.y;  t = upk2(q21); c2.z = t.x; c2.w = t.y;
    t = upk2(q30); c3.x = t.x; c3.y = t.y;  t = upk2(q31); c3.z = t.x; c3.w = t.y;

    int gr0 = row0 + 4 * ty;
    if (gr0 + 0 < N_NODES) *(float4*)(d_hp + (gr0 + 0) * 64 + 4 * tx) = c0;
    if (gr0 + 1 < N_NODES) *(float4*)(d_hp + (gr0 + 1) * 64 + 4 * tx) = c1;
    if (gr0 + 2 < N_NODES) *(float4*)(d_hp + (gr0 + 2) * 64 + 4 * tx) = c2;
    if (gr0 + 3 < N_NODES) *(float4*)(d_hp + (gr0 + 3) * 64 + 4 * tx) = c3;

    // fused logits: per-row dot with as/ad, reduce over tx (lane bits 0..3)
    float4 a4 = *(const float4*)&as[4 * tx];
    float4 d4 = *(const float4*)&ad[4 * tx];
    float rs0 = c0.x*a4.x + c0.y*a4.y + c0.z*a4.z + c0.w*a4.w;
    float rs1 = c1.x*a4.x + c1.y*a4.y + c1.z*a4.z + c1.w*a4.w;
    float rs2 = c2.x*a4.x + c2.y*a4.y + c2.z*a4.z + c2.w*a4.w;
    float rs3 = c3.x*a4.x + c3.y*a4.y + c3.z*a4.z + c3.w*a4.w;
    float rd0 = c0.x*d4.x + c0.y*d4.y + c0.z*d4.z + c0.w*d4.w;
    float rd1 = c1.x*d4.x + c1.y*d4.y + c1.z*d4.z + c1.w*d4.w;
    float rd2 = c2.x*d4.x + c2.y*d4.y + c2.z*d4.z + c2.w*d4.w;
    float rd3 = c3.x*d4.x + c3.y*d4.y + c3.z*d4.z + c3.w*d4.w;
#pragma unroll
    for (int o = 1; o < 16; o <<= 1) {
        rs0 += __shfl_xor_sync(0xffffffffu, rs0, o);
        rs1 += __shfl_xor_sync(0xffffffffu, rs1, o);
        rs2 += __shfl_xor_sync(0xffffffffu, rs2, o);
        rs3 += __shfl_xor_sync(0xffffffffu, rs3, o);
        rd0 += __shfl_xor_sync(0xffffffffu, rd0, o);
        rd1 += __shfl_xor_sync(0xffffffffu, rd1, o);
        rd2 += __shfl_xor_sync(0xffffffffu, rd2, o);
        rd3 += __shfl_xor_sync(0xffffffffu, rd3, o);
    }
    if (tx == 0) {
        if (gr0 + 0 < N_NODES) { d_esrc[gr0 + 0] = rs0; d_edst[gr0 + 0] = rd0; }
        if (gr0 + 1 < N_NODES) { d_esrc[gr0 + 1] = rs1; d_edst[gr0 + 1] = rd1; }
        if (gr0 + 2 < N_NODES) { d_esrc[gr0 + 2] = rs2; d_edst[gr0 + 2] = rd2; }
        if (gr0 + 3 < N_NODES) { d_esrc[gr0 + 3] = rs3; d_edst[gr0 + 3] = rd3; }
    }
}

// softmax aggregation: warp per node, attention weights staged per-chunk
// through shared memory (no global ea round-trip). No max-shift (logits O(1),
// softmax shift-invariant).
__global__ __launch_bounds__(256) void k_agg(const float* __restrict__ bias,
                                             int out_sel, int layer) {
    __shared__ float s_w[8][64];
    __shared__ float s_sum[64], s_sq[64];
    int tid = threadIdx.x;
    if (tid < 64) { s_sum[tid] = 0.f; s_sq[tid] = 0.f; }
    __syncthreads();
    int wid = tid >> 5, lane = tid & 31;
    int n = blockIdx.x * 8 + wid;
    int beg = d_rowstart[n], end = d_rowstart[n + 1];
    float ed = d_edst[n];
    int half = lane >> 4, q = lane & 15;
    const float4* hp4 = (const float4*)d_hp;

    float z = 0.f;
    float4 acc0 = {0,0,0,0}, acc1 = {0,0,0,0};
    for (int base = beg; base < end; base += 64) {
        int cnt = end - base; if (cnt > 64) cnt = 64;
        // step 1: compute w for this chunk into smem; accumulate z
        for (int j = lane; j < cnt; j += 32) {
            int s = d_csr[base + j];
            float e = d_esrc[s] + ed; e = e > 0.f ? e : NEG * e;
            float w = __expf(e);
            s_w[wid][j] = w;
            z += w;
        }
        __syncwarp();
        // step 2: weighted gather, 2 edges per warp-iter, float4 lanes
        int j = 0;
        for (; j + 4 <= cnt; j += 4) {
            int j0 = j + half, j1 = j + 2 + half;
            float w0 = s_w[wid][j0], w1 = s_w[wid][j1];
            int s0 = d_csr[base + j0], s1 = d_csr[base + j1];
            float4 h0 = hp4[s0 * 16 + q];
            float4 h1 = hp4[s1 * 16 + q];
            acc0.x += w0 * h0.x; acc0.y += w0 * h0.y; acc0.z += w0 * h0.z; acc0.w += w0 * h0.w;
            acc1.x += w1 * h1.x; acc1.y += w1 * h1.y; acc1.z += w1 * h1.z; acc1.w += w1 * h1.w;
        }
        for (; j < cnt; j += 2) {
            int jj = j + half;
            float w0 = 0.f; int s0 = 0;
            if (jj < cnt) { w0 = s_w[wid][jj]; s0 = d_csr[base + jj]; }
            float4 h0 = hp4[s0 * 16 + q];
            acc0.x += w0 * h0.x; acc0.y += w0 * h0.y; acc0.z += w0 * h0.z; acc0.w += w0 * h0.w;
        }
        __syncwarp();
    }
#pragma unroll
    for (int o = 16; o; o >>= 1) z += __shfl_xor_sync(0xffffffffu, z, o);
    float invz = 1.0f / z;

    acc0.x += acc1.x; acc0.y += acc1.y; acc0.z += acc1.z; acc0.w += acc1.w;
    acc0.x += __shfl_xor_sync(0xffffffffu, acc0.x, 16);
    acc0.y += __shfl_xor_sync(0xffffffffu, acc0.y, 16);
    acc0.z += __shfl_xor_sync(0xffffffffu, acc0.z, 16);
    acc0.w += __shfl_xor_sync(0xffffffffu, acc0.w, 16);
    if (half == 0) {
        float4 b4 = *(const float4*)&bias[4 * q];
        float4 v;
        v.x = acc0.x * invz + b4.x;
        v.y = acc0.y * invz + b4.y;
        v.z = acc0.z * invz + b4.z;
        v.w = acc0.w * invz + b4.w;
        float4* out4 = (float4*)((out_sel == 1) ? d_hA : d_hB);
        out4[n * 16 + q] = v;
        int c = 4 * q;
        atomicAdd(&s_sum[c + 0], v.x); atomicAdd(&s_sq[c + 0], v.x * v.x);
        atomicAdd(&s_sum[c + 1], v.y); atomicAdd(&s_sq[c + 1], v.y * v.y);
        atomicAdd(&s_sum[c + 2], v.z); atomicAdd(&s_sq[c + 2], v.z * v.z);
        atomicAdd(&s_sum[c + 3], v.w); atomicAdd(&s_sq[c + 3], v.w * v.w);
    }
    __syncthreads();
    if (tid < 64) {
        atomicAdd(&d_gsum[layer][tid], s_sum[tid]);
        atomicAdd(&d_gsq[layer][tid], s_sq[tid]);
    }
}

// global mean pool, BN of last layer computed inline
__global__ __launch_bounds__(256) void k_pool(int src_sel, const void* batch,
                                              const float* __restrict__ gm,
                                              const float* __restrict__ bt) {
    __shared__ float s_pool[64];
    __shared__ float s_sc[64], s_sh[64];
    __shared__ int s_cnt;
    __shared__ int s_g0;
    int tid = threadIdx.x;
    int lane = tid & 31;
    if (tid < 64) {
        s_pool[tid] = 0.f;
        float mu = d_gsum[N_LAYERS - 1][tid] * (1.0f / N_NODES);
        float var = d_gsq[N_LAYERS - 1][tid] * (1.0f / N_NODES) - mu * mu;
        float s = gm[tid] * rsqrtf(var + BN_EPS);
        s_sc[tid] = s;
        s_sh[tid] = bt[tid] - mu * s;
    }
    if (tid == 0) {
        s_cnt = 0;
        int n0 = blockIdx.x * 8;
        s_g0 = d_flag_b ? (int)((const long long*)batch)[n0] : ((const int*)batch)[n0];
    }
    __syncthreads();
    int n = blockIdx.x * 8 + (tid >> 5);
    const float* h = (src_sel == 1) ? d_hA : d_hB;
    int g = d_flag_b ? (int)((const long long*)batch)[n] : ((const int*)batch)[n];
    int c0 = 2 * lane, c1 = c0 + 1;
    float v0 = fmaxf(h[n * 64 + c0] * s_sc[c0] + s_sh[c0], 0.f);
    float v1 = fmaxf(h[n * 64 + c1] * s_sc[c1] + s_sh[c1], 0.f);
    if (g == s_g0) {
        atomicAdd(&s_pool[c0], v0);
        atomicAdd(&s_pool[c1], v1);
        if (!lane) atomicAdd(&s_cnt, 1);
    } else {
        atomicAdd(&d_pooled[g * 64 + c0], v0);
        atomicAdd(&d_pooled[g * 64 + c1], v1);
        if (!lane) atomicAdd(&d_cnt[g], 1.0f);
    }
    __syncthreads();
    if (tid < 64) atomicAdd(&d_pooled[s_g0 * 64 + tid], s_pool[tid]);
    if (tid == 64) atomicAdd(&d_cnt[s_g0], (float)s_cnt);
}

__global__ void k_mlp(const float* __restrict__ W1, const float* __restrict__ b1,
                      const float* __restrict__ W2, const float* __restrict__ b2,
                      const float* __restrict__ W3, const float* __restrict__ b3,
                      float* __restrict__ out) {
    int g = threadIdx.x;
    if (g >= N_GRAPHS) return;
    float inv = 1.0f / fmaxf(d_cnt[g], 1.0f);
    float p[64];
    for (int i = 0; i < 64; i++) p[i] = d_pooled[g * 64 + i] * inv;
    float h1[50];
    for (int j = 0; j < 50; j++) {
        float s = b1[j];
        for (int i = 0; i < 64; i++) s += p[i] * W1[i * 50 + j];
        h1[j] = fmaxf(s, 0.f);
    }
    float h2[25];
    for (int j = 0; j < 25; j++) {
        float s = b2[j];
        for (int i = 0; i < 50; i++) s += h1[i] * W2[i * 25 + j];
        h2[j] = fmaxf(s, 0.f);
    }
    float s = b3[0];
    for (int i = 0; i < 25; i++) s += h2[i] * W3[i];
    out[g] = s;
}

extern "C" void kernel_launch(void* const* d_in, const int* in_sizes, int n_in,
                              void* d_out, int out_size) {
    const float* x       = (const float*)d_in[0];
    const float* W0      = (const float*)d_in[1];
    const float* Ws      = (const float*)d_in[2];
    const float* att_src = (const float*)d_in[3];
    const float* att_dst = (const float*)d_in[4];
    const float* bias    = (const float*)d_in[5];
    const float* gamma   = (const float*)d_in[6];
    const float* beta    = (const float*)d_in[7];
    const float* mW1 = (const float*)d_in[8];
    const float* mb1 = (const float*)d_in[9];
    const float* mW2 = (const float*)d_in[10];
    const float* mb2 = (const float*)d_in[11];
    const float* mW3 = (const float*)d_in[12];
    const float* mb3 = (const float*)d_in[13];
    const void*  eidx  = d_in[14];
    const void*  batch = d_in[15];

    k_zero<<<(N_NODES + 255) / 256, 256>>>();
    k_detect<<<1, 256>>>(eidx, (long)N_EDGES, (long long)N_NODES, 0);
    k_detect<<<1, 256>>>(batch, (long)(N_NODES / 2), (long long)N_GRAPHS, 1);
    k_build<<<(E_TOT + 255) / 256, 256>>>(eidx);
    k_scan1<<<SCAN_BLOCKS, 1024>>>();
    k_scan2<<<1, 128>>>();
    k_scan3<<<SCAN_BLOCKS, 1024>>>();
    k_scatter<<<(E_TOT + 255) / 256, 256>>>();

    for (int l = 0; l < N_LAYERS; l++) {
        const float* W = (l == 0) ? W0 : (Ws + (size_t)(l - 1) * HID * HID);
        int src_sel = (l == 0) ? 0 : ((l & 1) ? 1 : 2);
        int out_sel = (l & 1) ? 2 : 1;
        const float* gm = gamma + (l > 0 ? (l - 1) : 0) * HID;
        const float* bt = beta + (l > 0 ? (l - 1) : 0) * HID;
        k_gemm<<<(N_NODES + 63) / 64, 256>>>(x, src_sel, W, l - 1,
                                             att_src + l * HID, att_dst + l * HID,
                                             gm, bt);
        k_agg<<<12500, 256>>>(bias + l * HID, out_sel, l);
    }
    k_pool<<<12500, 256>>>(2, batch, gamma + 15 * HID, beta + 15 * HID);
    k_mlp<<<1, 64>>>(mW1, mb1, mW2, mb2, mW3, mb3, (float*)d_out);
}